// round 2
// baseline (speedup 1.0000x reference)
#include <cuda_runtime.h>
#include <math.h>

#define NTS      4096
#define SEQ_LEN  168
#define HORIZON  24
#define TTOT     (SEQ_LEN + HORIZON)
#define F_IN     32
#define EMBED    32
#define HIDDEN   64
#define LAYERS   2

#define SW_FLOATS   (2 * 192 * 64)
#define SB_FLOATS   (2 * 192)
#define SMALL_FLOATS (32 + 32 + 64 + 64)
#define SMEM_FLOATS (SW_FLOATS + SB_FLOATS + SMALL_FLOATS + 8 * 64)

#define BLK     256
#define GRID_B  512                      /* 512 blocks x 8 warps = 4096 series */
#define ITEMS_A (NTS * SEQ_LEN)          /* 688128 */
#define GRID_A  ((ITEMS_A * 2) / BLK)    /* 5376: 2 threads per item */

typedef unsigned long long u64;

__device__ __forceinline__ float sigm(float x) { return 1.0f / (1.0f + expf(-x)); }
__device__ __forceinline__ float softplus_(float x) {
    return (x > 20.0f) ? x : log1pf(expf(x));
}
__device__ __forceinline__ int src_row(int r) { return r + ((r >= 64) ? 64 : 0); }

__device__ __forceinline__ u64 pack2(float lo, float hi) {
    u64 r; asm("mov.b64 %0, {%1,%2};" : "=l"(r) : "f"(lo), "f"(hi)); return r;
}
__device__ __forceinline__ void unpack2(u64 v, float& a, float& b) {
    asm("mov.b64 {%0,%1}, %2;" : "=f"(a), "=f"(b) : "l"(v));
}
__device__ __forceinline__ u64 ffma2(u64 a, u64 b, u64 c) {
    u64 d; asm("fma.rn.f32x2 %0, %1, %2, %3;" : "=l"(d) : "l"(a), "l"(b), "l"(c));
    return d;
}

__global__ void __launch_bounds__(BLK, 2) deepar_fused(
    const float* __restrict__ X, const float* __restrict__ y,
    const float* __restrict__ Xf,
    const float* __restrict__ W_embed, const float* __restrict__ b_embed,
    const float* __restrict__ W_ih, const float* __restrict__ b_ih,
    const float* __restrict__ b_hh,
    const float* __restrict__ W_mu, const float* __restrict__ b_mu,
    const float* __restrict__ W_sigma, const float* __restrict__ b_sigma,
    float* __restrict__ out)
{
    extern __shared__ float sm[];
    float* sW   = sm;                 // A: [2][192][64] row-major; B: [2][64][192] transposed
    float* sB   = sW + SW_FLOATS;     // [2][192]
    float* sWe  = sB + SB_FLOATS;
    float* sBe  = sWe + 32;
    float* sWmu = sBe + 32;
    float* sWsg = sWmu + 64;
    float* sH   = sWsg + 64;          // B only: [8 warps][64]

    const int tid = threadIdx.x;
    const bool isB = (blockIdx.x < GRID_B);

    // ---- load weights into smem (layout depends on role) ----
    for (int idx = tid; idx < SW_FLOATS; idx += BLK) {
        int l = idx / 12288, rem = idx % 12288;
        int r = rem / 64, k = rem % 64;
        float v = W_ih[l * 16384 + src_row(r) * 64 + k];
        if (isB) sW[l * 12288 + k * 192 + r] = v;   // transposed
        else     sW[idx] = v;                        // row-major
    }
    for (int idx = tid; idx < SB_FLOATS; idx += BLK) {
        int l = idx / 192, r = idx % 192;
        int sr = l * 256 + src_row(r);
        sB[idx] = b_ih[sr] + b_hh[sr];
    }
    if (tid < 32) { sWe[tid] = W_embed[tid]; sBe[tid] = b_embed[tid]; }
    if (tid < 64) { sWmu[tid] = W_mu[tid]; sWsg[tid] = W_sigma[tid]; }
    __syncthreads();

    float* out_mu = out + NTS * HORIZON;
    float* out_sg = out_mu + NTS * TTOT;

    if (!isB) {
        // =================== Phase A: teacher-forced steps =================
        // Two threads per (n,t) item; thread handles 32 of 64 hidden units.
        const int aThread = (blockIdx.x - GRID_B) * BLK + tid;
        const int item = aThread >> 1;
        const int half = aThread & 1;
        const int n = item / SEQ_LEN;
        const int t = item % SEQ_LEN;
        const int jb = half * 32;

        // build packed input h2[32] = (h[2p], h[2p+1])
        u64 h2[32];
        const float4* xp = (const float4*)(X + (size_t)item * F_IN);
        #pragma unroll
        for (int q = 0; q < 8; ++q) {
            float4 v = xp[q];
            h2[2 * q]     = pack2(v.x, v.y);
            h2[2 * q + 1] = pack2(v.z, v.w);
        }
        const float yn = y[item];
        #pragma unroll
        for (int e = 0; e < 16; ++e)
            h2[16 + e] = pack2(fmaf(yn, sWe[2 * e], sBe[2 * e]),
                               fmaf(yn, sWe[2 * e + 1], sBe[2 * e + 1]));

        // ---- layer 1: compute own 32 outputs ----
        float hn[32];
        {
            const float* W = sW;           // layer 0 base
            const float* B = sB;
            for (int jj = 0; jj < 32; ++jj) {
                const int j = jb + jj;
                const ulonglong2* wi = (const ulonglong2*)(W + j * 64);
                const ulonglong2* wg = (const ulonglong2*)(W + (64 + j) * 64);
                const ulonglong2* wo = (const ulonglong2*)(W + (128 + j) * 64);
                u64 ai = pack2(B[j], 0.0f);
                u64 ag = pack2(B[64 + j], 0.0f);
                u64 ao = pack2(B[128 + j], 0.0f);
                #pragma unroll
                for (int k4 = 0; k4 < 16; ++k4) {
                    ulonglong2 vi = wi[k4], vg = wg[k4], vo = wo[k4];
                    ai = ffma2(vi.x, h2[2 * k4], ai);
                    ag = ffma2(vg.x, h2[2 * k4], ag);
                    ao = ffma2(vo.x, h2[2 * k4], ao);
                    ai = ffma2(vi.y, h2[2 * k4 + 1], ai);
                    ag = ffma2(vg.y, h2[2 * k4 + 1], ag);
                    ao = ffma2(vo.y, h2[2 * k4 + 1], ao);
                }
                float a0, a1, g0, g1, o0, o1;
                unpack2(ai, a0, a1); unpack2(ag, g0, g1); unpack2(ao, o0, o1);
                float ais = a0 + a1, ags = g0 + g1, aos = o0 + o1;
                float c = sigm(ais) * tanhf(ags);
                hn[jj] = sigm(aos) * tanhf(c);
            }
        }

        // exchange halves with partner thread -> full layer-2 input
        #pragma unroll
        for (int q = 0; q < 16; ++q) {
            float a0 = hn[2 * q], a1 = hn[2 * q + 1];
            float b0 = __shfl_xor_sync(0xFFFFFFFFu, a0, 1);
            float b1 = __shfl_xor_sync(0xFFFFFFFFu, a1, 1);
            h2[half * 16 + q]       = pack2(a0, a1);
            h2[(1 ^ half) * 16 + q] = pack2(b0, b1);
        }

        // ---- layer 2 + fused head (own 32 outputs) ----
        float pm = 0.0f, ps = 0.0f;
        {
            const float* W = sW + 12288;   // layer 1 base
            const float* B = sB + 192;
            for (int jj = 0; jj < 32; ++jj) {
                const int j = jb + jj;
                const ulonglong2* wi = (const ulonglong2*)(W + j * 64);
                const ulonglong2* wg = (const ulonglong2*)(W + (64 + j) * 64);
                const ulonglong2* wo = (const ulonglong2*)(W + (128 + j) * 64);
                u64 ai = pack2(B[j], 0.0f);
                u64 ag = pack2(B[64 + j], 0.0f);
                u64 ao = pack2(B[128 + j], 0.0f);
                #pragma unroll
                for (int k4 = 0; k4 < 16; ++k4) {
                    ulonglong2 vi = wi[k4], vg = wg[k4], vo = wo[k4];
                    ai = ffma2(vi.x, h2[2 * k4], ai);
                    ag = ffma2(vg.x, h2[2 * k4], ag);
                    ao = ffma2(vo.x, h2[2 * k4], ao);
                    ai = ffma2(vi.y, h2[2 * k4 + 1], ai);
                    ag = ffma2(vg.y, h2[2 * k4 + 1], ag);
                    ao = ffma2(vo.y, h2[2 * k4 + 1], ao);
                }
                float a0, a1, g0, g1, o0, o1;
                unpack2(ai, a0, a1); unpack2(ag, g0, g1); unpack2(ao, o0, o1);
                float ais = a0 + a1, ags = g0 + g1, aos = o0 + o1;
                float c = sigm(ais) * tanhf(ags);
                float hj = sigm(aos) * tanhf(c);
                float r = fmaxf(hj, 0.0f);
                pm = fmaf(r, sWmu[j], pm);
                ps = fmaf(r, sWsg[j], ps);
            }
        }
        pm += __shfl_xor_sync(0xFFFFFFFFu, pm, 1);
        ps += __shfl_xor_sync(0xFFFFFFFFu, ps, 1);

        if (half == 0) {
            float mu = pm + b_mu[0];
            float sigma = softplus_(ps + b_sigma[0]) + 1e-6f;
            out_mu[n * TTOT + t] = mu;
            out_sg[n * TTOT + t] = sigma;
        }
        return;
    }

    // ====================== Phase B: horizon steps =========================
    const int lane = tid & 31;
    const int wl   = tid >> 5;
    const int n    = blockIdx.x * 8 + wl;

    float* sh = sH + wl * 64;
    const float bmu = b_mu[0], bsg = b_sigma[0];
    const float we = sWe[lane], be = sBe[lane];
    const float wmu0 = sWmu[lane], wmu1 = sWmu[32 + lane];
    const float wsg0 = sWsg[lane], wsg1 = sWsg[32 + lane];

    float carry = 0.0f;

    // sp == 0: seed step (t = SEQ_LEN-1, teacher forced) -> produces carry &
    // ypred[:,0]. sp in [1, HORIZON]: horizon step t = SEQ_LEN + sp - 1.
    for (int sp = 0; sp <= HORIZON; ++sp) {
        const bool seed = (sp == 0);
        const float yn = seed ? y[(size_t)n * SEQ_LEN + (SEQ_LEN - 1)] : carry;
        const float* xsrc = seed
            ? (X + ((size_t)n * SEQ_LEN + (SEQ_LEN - 1)) * F_IN)
            : (Xf + ((size_t)n * HORIZON + (sp - 1)) * F_IN);

        sh[lane]      = xsrc[lane];
        sh[32 + lane] = fmaf(yn, we, be);
        __syncwarp();

        #pragma unroll
        for (int l = 0; l < LAYERS; ++l) {
            const float* WT = sW + l * 12288;
            const float* B  = sB + l * 192;
            float a0 = B[lane],      a1 = B[64 + lane],  a2 = B[128 + lane];
            float a3 = B[32 + lane], a4 = B[96 + lane],  a5 = B[160 + lane];
            #pragma unroll
            for (int k = 0; k < 64; ++k) {
                const float hk = sh[k];
                const float* row = WT + k * 192;
                a0 = fmaf(row[lane],       hk, a0);
                a1 = fmaf(row[64 + lane],  hk, a1);
                a2 = fmaf(row[128 + lane], hk, a2);
                a3 = fmaf(row[32 + lane],  hk, a3);
                a4 = fmaf(row[96 + lane],  hk, a4);
                a5 = fmaf(row[160 + lane], hk, a5);
            }
            float c0 = sigm(a0) * tanhf(a1);
            float h0 = sigm(a2) * tanhf(c0);
            float c1 = sigm(a3) * tanhf(a4);
            float h1 = sigm(a5) * tanhf(c1);
            __syncwarp();
            sh[lane] = h0; sh[32 + lane] = h1;
            __syncwarp();
        }

        float r0 = fmaxf(sh[lane], 0.0f), r1 = fmaxf(sh[32 + lane], 0.0f);
        float pm = r0 * wmu0 + r1 * wmu1;
        float ps = r0 * wsg0 + r1 * wsg1;
        #pragma unroll
        for (int off = 16; off; off >>= 1) {
            pm += __shfl_xor_sync(0xFFFFFFFFu, pm, off);
            ps += __shfl_xor_sync(0xFFFFFFFFu, ps, off);
        }
        float mu = pm + bmu;
        float sigma = softplus_(ps + bsg) + 1e-6f;
        float s2 = sigma * sigma;
        float d = yn - mu;
        float lik = rsqrtf(2.0f * (float)M_PI * s2) * expf(-(d * d) / (2.0f * s2));

        if (lane == 0) {
            if (seed) {
                out[n * HORIZON] = lik;    // ypred[:,0] = lik at t = SEQ_LEN-1
            } else {
                const int t = SEQ_LEN + sp - 1;
                out_mu[n * TTOT + t] = mu;
                out_sg[n * TTOT + t] = sigma;
                if (sp <= HORIZON - 1)
                    out[n * HORIZON + sp] = lik;
            }
        }
        carry = lik;
    }
}

extern "C" void kernel_launch(void* const* d_in, const int* in_sizes, int n_in,
                              void* d_out, int out_size)
{
    const float* X       = (const float*)d_in[0];
    const float* y       = (const float*)d_in[1];
    const float* Xf      = (const float*)d_in[2];
    const float* W_embed = (const float*)d_in[3];
    const float* b_embed = (const float*)d_in[4];
    const float* W_ih    = (const float*)d_in[5];
    const float* b_ih    = (const float*)d_in[6];
    const float* b_hh    = (const float*)d_in[7];
    const float* W_mu    = (const float*)d_in[8];
    const float* b_mu    = (const float*)d_in[9];
    const float* W_sigma = (const float*)d_in[10];
    const float* b_sigma = (const float*)d_in[11];
    float* out = (float*)d_out;

    static bool attr_done = false;
    if (!attr_done) {
        cudaFuncSetAttribute(deepar_fused,
            cudaFuncAttributeMaxDynamicSharedMemorySize, SMEM_FLOATS * 4);
        attr_done = true;
    }

    deepar_fused<<<GRID_B + GRID_A, BLK, SMEM_FLOATS * 4>>>(
        X, y, Xf, W_embed, b_embed, W_ih, b_ih, b_hh,
        W_mu, b_mu, W_sigma, b_sigma, out);
}

// round 3
// speedup vs baseline: 1.7119x; 1.7119x over previous
#include <cuda_runtime.h>
#include <math.h>

#define NTS      4096
#define SEQ_LEN  168
#define HORIZON  24
#define TTOT     (SEQ_LEN + HORIZON)
#define F_IN     32
#define EMBED    32
#define HIDDEN   64
#define LAYERS   2

#define SW_FLOATS   (2 * 192 * 64)
#define SB_FLOATS   (2 * 192)
#define SMALL_FLOATS (32 + 32 + 64 + 64)
#define SMEM_FLOATS (SW_FLOATS + SB_FLOATS + SMALL_FLOATS + 8 * 64)

#define BLK     256
#define GRID_B  512                      /* 512 x 8 warps = 4096 series */
#define ITEMS_A (NTS * SEQ_LEN)          /* 688128 */
#define GRID_A  (ITEMS_A / BLK)          /* 2688: 1 thread per item */

typedef unsigned long long u64;

__device__ __forceinline__ float ex2f(float x) {
    float r; asm("ex2.approx.f32 %0, %1;" : "=f"(r) : "f"(x)); return r;
}
__device__ __forceinline__ float rcpf(float x) {
    float r; asm("rcp.approx.f32 %0, %1;" : "=f"(r) : "f"(x)); return r;
}
// sigm(x) = 1/(1+2^(-x*log2e));  tanh(x) = 1 - 2/(1+2^(x*2*log2e))
__device__ __forceinline__ float sigm(float x) {
    return rcpf(1.0f + ex2f(-1.4426950408889634f * x));
}
__device__ __forceinline__ float tanh_(float x) {
    return 1.0f - 2.0f * rcpf(1.0f + ex2f(2.8853900817779268f * x));
}
__device__ __forceinline__ float softplus_(float x) {
    return (x > 20.0f) ? x : log1pf(ex2f(1.4426950408889634f * x));
}
__device__ __forceinline__ int src_row(int r) { return r + ((r >= 64) ? 64 : 0); }

__device__ __forceinline__ u64 pack2(float lo, float hi) {
    u64 r; asm("mov.b64 %0, {%1,%2};" : "=l"(r) : "f"(lo), "f"(hi)); return r;
}
__device__ __forceinline__ void unpack2(u64 v, float& a, float& b) {
    asm("mov.b64 {%0,%1}, %2;" : "=f"(a), "=f"(b) : "l"(v));
}
__device__ __forceinline__ u64 ffma2(u64 a, u64 b, u64 c) {
    u64 d; asm("fma.rn.f32x2 %0, %1, %2, %3;" : "=l"(d) : "l"(a), "l"(b), "l"(c));
    return d;
}

__global__ void __launch_bounds__(BLK, 2) deepar_fused(
    const float* __restrict__ X, const float* __restrict__ y,
    const float* __restrict__ Xf,
    const float* __restrict__ W_embed, const float* __restrict__ b_embed,
    const float* __restrict__ W_ih, const float* __restrict__ b_ih,
    const float* __restrict__ b_hh,
    const float* __restrict__ W_mu, const float* __restrict__ b_mu,
    const float* __restrict__ W_sigma, const float* __restrict__ b_sigma,
    float* __restrict__ out)
{
    extern __shared__ float sm[];
    float* sW   = sm;                 // A: [2][192][64] row-major; B: [2][64][192] transposed
    float* sB   = sW + SW_FLOATS;     // [2][192]
    float* sWe  = sB + SB_FLOATS;
    float* sBe  = sWe + 32;
    float* sWmu = sBe + 32;
    float* sWsg = sWmu + 64;
    float* sH   = sWsg + 64;          // B role only: [8 warps][64]

    const int tid = threadIdx.x;
    const bool isB = (blockIdx.x < GRID_B);

    for (int idx = tid; idx < SW_FLOATS; idx += BLK) {
        int l = idx / 12288, rem = idx % 12288;
        int r = rem / 64, k = rem % 64;
        float v = W_ih[l * 16384 + src_row(r) * 64 + k];
        if (isB) sW[l * 12288 + k * 192 + r] = v;
        else     sW[idx] = v;
    }
    for (int idx = tid; idx < SB_FLOATS; idx += BLK) {
        int l = idx / 192, r = idx % 192;
        int sr = l * 256 + src_row(r);
        sB[idx] = b_ih[sr] + b_hh[sr];
    }
    if (tid < 32) { sWe[tid] = W_embed[tid]; sBe[tid] = b_embed[tid]; }
    if (tid < 64) { sWmu[tid] = W_mu[tid]; sWsg[tid] = W_sigma[tid]; }
    __syncthreads();

    float* out_mu = out + NTS * HORIZON;
    float* out_sg = out_mu + NTS * TTOT;

    if (!isB) {
        // =================== Phase A: one thread per (n,t) item ===========
        const int item = (blockIdx.x - GRID_B) * BLK + tid;
        const int n = item / SEQ_LEN;
        const int t = item % SEQ_LEN;

        u64 h2[32];                    // packed pairs (h[2q], h[2q+1])
        const float4* xp = (const float4*)(X + (size_t)item * F_IN);
        #pragma unroll
        for (int q = 0; q < 8; ++q) {
            float4 v = xp[q];
            h2[2 * q]     = pack2(v.x, v.y);
            h2[2 * q + 1] = pack2(v.z, v.w);
        }
        const float yn = y[item];
        #pragma unroll
        for (int e = 0; e < 16; ++e)
            h2[16 + e] = pack2(fmaf(yn, sWe[2 * e], sBe[2 * e]),
                               fmaf(yn, sWe[2 * e + 1], sBe[2 * e + 1]));

        u64 nh2[32];
        // ---------------- layer 1: j-pairs, 6 independent chains ----------
        {
            const float* W = sW;
            const float* B = sB;
            #pragma unroll 1
            for (int jp = 0; jp < 32; ++jp) {
                const int j0 = 2 * jp, j1 = 2 * jp + 1;
                const ulonglong2* wi0 = (const ulonglong2*)(W + j0 * 64);
                const ulonglong2* wi1 = (const ulonglong2*)(W + j1 * 64);
                const ulonglong2* wg0 = (const ulonglong2*)(W + (64 + j0) * 64);
                const ulonglong2* wg1 = (const ulonglong2*)(W + (64 + j1) * 64);
                const ulonglong2* wo0 = (const ulonglong2*)(W + (128 + j0) * 64);
                const ulonglong2* wo1 = (const ulonglong2*)(W + (128 + j1) * 64);
                u64 ai0 = pack2(B[j0], 0.f),       ai1 = pack2(B[j1], 0.f);
                u64 ag0 = pack2(B[64 + j0], 0.f),  ag1 = pack2(B[64 + j1], 0.f);
                u64 ao0 = pack2(B[128 + j0], 0.f), ao1 = pack2(B[128 + j1], 0.f);
                #pragma unroll
                for (int k4 = 0; k4 < 16; ++k4) {
                    ulonglong2 vi0 = wi0[k4], vi1 = wi1[k4];
                    ulonglong2 vg0 = wg0[k4], vg1 = wg1[k4];
                    ulonglong2 vo0 = wo0[k4], vo1 = wo1[k4];
                    u64 ha = h2[2 * k4], hb = h2[2 * k4 + 1];
                    ai0 = ffma2(vi0.x, ha, ai0); ai0 = ffma2(vi0.y, hb, ai0);
                    ai1 = ffma2(vi1.x, ha, ai1); ai1 = ffma2(vi1.y, hb, ai1);
                    ag0 = ffma2(vg0.x, ha, ag0); ag0 = ffma2(vg0.y, hb, ag0);
                    ag1 = ffma2(vg1.x, ha, ag1); ag1 = ffma2(vg1.y, hb, ag1);
                    ao0 = ffma2(vo0.x, ha, ao0); ao0 = ffma2(vo0.y, hb, ao0);
                    ao1 = ffma2(vo1.x, ha, ao1); ao1 = ffma2(vo1.y, hb, ao1);
                }
                float x0, x1, y0_, y1_, z0, z1;
                unpack2(ai0, x0, x1); unpack2(ag0, y0_, y1_); unpack2(ao0, z0, z1);
                float c0 = sigm(x0 + x1) * tanh_(y0_ + y1_);
                float hj0 = sigm(z0 + z1) * tanh_(c0);
                unpack2(ai1, x0, x1); unpack2(ag1, y0_, y1_); unpack2(ao1, z0, z1);
                float c1 = sigm(x0 + x1) * tanh_(y0_ + y1_);
                float hj1 = sigm(z0 + z1) * tanh_(c1);
                nh2[jp] = pack2(hj0, hj1);
            }
        }
        #pragma unroll
        for (int q = 0; q < 32; ++q) h2[q] = nh2[q];

        // ---------------- layer 2 + fused head ----------------------------
        float pm = 0.0f, ps = 0.0f;
        {
            const float* W = sW + 12288;
            const float* B = sB + 192;
            #pragma unroll 1
            for (int jp = 0; jp < 32; ++jp) {
                const int j0 = 2 * jp, j1 = 2 * jp + 1;
                const ulonglong2* wi0 = (const ulonglong2*)(W + j0 * 64);
                const ulonglong2* wi1 = (const ulonglong2*)(W + j1 * 64);
                const ulonglong2* wg0 = (const ulonglong2*)(W + (64 + j0) * 64);
                const ulonglong2* wg1 = (const ulonglong2*)(W + (64 + j1) * 64);
                const ulonglong2* wo0 = (const ulonglong2*)(W + (128 + j0) * 64);
                const ulonglong2* wo1 = (const ulonglong2*)(W + (128 + j1) * 64);
                u64 ai0 = pack2(B[j0], 0.f),       ai1 = pack2(B[j1], 0.f);
                u64 ag0 = pack2(B[64 + j0], 0.f),  ag1 = pack2(B[64 + j1], 0.f);
                u64 ao0 = pack2(B[128 + j0], 0.f), ao1 = pack2(B[128 + j1], 0.f);
                #pragma unroll
                for (int k4 = 0; k4 < 16; ++k4) {
                    ulonglong2 vi0 = wi0[k4], vi1 = wi1[k4];
                    ulonglong2 vg0 = wg0[k4], vg1 = wg1[k4];
                    ulonglong2 vo0 = wo0[k4], vo1 = wo1[k4];
                    u64 ha = h2[2 * k4], hb = h2[2 * k4 + 1];
                    ai0 = ffma2(vi0.x, ha, ai0); ai0 = ffma2(vi0.y, hb, ai0);
                    ai1 = ffma2(vi1.x, ha, ai1); ai1 = ffma2(vi1.y, hb, ai1);
                    ag0 = ffma2(vg0.x, ha, ag0); ag0 = ffma2(vg0.y, hb, ag0);
                    ag1 = ffma2(vg1.x, ha, ag1); ag1 = ffma2(vg1.y, hb, ag1);
                    ao0 = ffma2(vo0.x, ha, ao0); ao0 = ffma2(vo0.y, hb, ao0);
                    ao1 = ffma2(vo1.x, ha, ao1); ao1 = ffma2(vo1.y, hb, ao1);
                }
                float x0, x1, y0_, y1_, z0, z1;
                unpack2(ai0, x0, x1); unpack2(ag0, y0_, y1_); unpack2(ao0, z0, z1);
                float c0 = sigm(x0 + x1) * tanh_(y0_ + y1_);
                float hj0 = sigm(z0 + z1) * tanh_(c0);
                unpack2(ai1, x0, x1); unpack2(ag1, y0_, y1_); unpack2(ao1, z0, z1);
                float c1 = sigm(x0 + x1) * tanh_(y0_ + y1_);
                float hj1 = sigm(z0 + z1) * tanh_(c1);
                float r0 = fmaxf(hj0, 0.0f), r1 = fmaxf(hj1, 0.0f);
                pm = fmaf(r0, sWmu[j0], pm); pm = fmaf(r1, sWmu[j1], pm);
                ps = fmaf(r0, sWsg[j0], ps); ps = fmaf(r1, sWsg[j1], ps);
            }
        }

        float mu = pm + b_mu[0];
        float sigma = softplus_(ps + b_sigma[0]) + 1e-6f;
        out_mu[n * TTOT + t] = mu;
        out_sg[n * TTOT + t] = sigma;
        return;
    }

    // ====================== Phase B: horizon steps =========================
    const int lane = tid & 31;
    const int wl   = tid >> 5;
    const int n    = blockIdx.x * 8 + wl;

    float* sh = sH + wl * 64;
    const float bmu = b_mu[0], bsg = b_sigma[0];
    const float we = sWe[lane], be = sBe[lane];
    const float wmu0 = sWmu[lane], wmu1 = sWmu[32 + lane];
    const float wsg0 = sWsg[lane], wsg1 = sWsg[32 + lane];

    float carry = 0.0f;
    for (int sp = 0; sp <= HORIZON; ++sp) {
        const bool seed = (sp == 0);
        const float yn = seed ? y[(size_t)n * SEQ_LEN + (SEQ_LEN - 1)] : carry;
        const float* xsrc = seed
            ? (X + ((size_t)n * SEQ_LEN + (SEQ_LEN - 1)) * F_IN)
            : (Xf + ((size_t)n * HORIZON + (sp - 1)) * F_IN);

        sh[lane]      = xsrc[lane];
        sh[32 + lane] = fmaf(yn, we, be);
        __syncwarp();

        #pragma unroll
        for (int l = 0; l < LAYERS; ++l) {
            const float* WT = sW + l * 12288;
            const float* B  = sB + l * 192;
            float a0 = B[lane],      a1 = B[64 + lane],  a2 = B[128 + lane];
            float a3 = B[32 + lane], a4 = B[96 + lane],  a5 = B[160 + lane];
            #pragma unroll
            for (int k = 0; k < 64; ++k) {
                const float hk = sh[k];
                const float* row = WT + k * 192;
                a0 = fmaf(row[lane],       hk, a0);
                a1 = fmaf(row[64 + lane],  hk, a1);
                a2 = fmaf(row[128 + lane], hk, a2);
                a3 = fmaf(row[32 + lane],  hk, a3);
                a4 = fmaf(row[96 + lane],  hk, a4);
                a5 = fmaf(row[160 + lane], hk, a5);
            }
            float c0 = sigm(a0) * tanh_(a1);
            float h0 = sigm(a2) * tanh_(c0);
            float c1 = sigm(a3) * tanh_(a4);
            float h1 = sigm(a5) * tanh_(c1);
            __syncwarp();
            sh[lane] = h0; sh[32 + lane] = h1;
            __syncwarp();
        }

        float r0 = fmaxf(sh[lane], 0.0f), r1 = fmaxf(sh[32 + lane], 0.0f);
        float pm = r0 * wmu0 + r1 * wmu1;
        float ps = r0 * wsg0 + r1 * wsg1;
        #pragma unroll
        for (int off = 16; off; off >>= 1) {
            pm += __shfl_xor_sync(0xFFFFFFFFu, pm, off);
            ps += __shfl_xor_sync(0xFFFFFFFFu, ps, off);
        }
        float mu = pm + bmu;
        float sigma = softplus_(ps + bsg) + 1e-6f;
        float s2 = sigma * sigma;
        float d = yn - mu;
        float lik = rsqrtf(2.0f * (float)M_PI * s2) *
                    ex2f(-1.4426950408889634f * (d * d) / (2.0f * s2));

        if (lane == 0) {
            if (seed) {
                out[n * HORIZON] = lik;
            } else {
                const int t = SEQ_LEN + sp - 1;
                out_mu[n * TTOT + t] = mu;
                out_sg[n * TTOT + t] = sigma;
                if (sp <= HORIZON - 1)
                    out[n * HORIZON + sp] = lik;
            }
        }
        carry = lik;
    }
}

extern "C" void kernel_launch(void* const* d_in, const int* in_sizes, int n_in,
                              void* d_out, int out_size)
{
    const float* X       = (const float*)d_in[0];
    const float* y       = (const float*)d_in[1];
    const float* Xf      = (const float*)d_in[2];
    const float* W_embed = (const float*)d_in[3];
    const float* b_embed = (const float*)d_in[4];
    const float* W_ih    = (const float*)d_in[5];
    const float* b_ih    = (const float*)d_in[6];
    const float* b_hh    = (const float*)d_in[7];
    const float* W_mu    = (const float*)d_in[8];
    const float* b_mu    = (const float*)d_in[9];
    const float* W_sigma = (const float*)d_in[10];
    const float* b_sigma = (const float*)d_in[11];
    float* out = (float*)d_out;

    static bool attr_done = false;
    if (!attr_done) {
        cudaFuncSetAttribute(deepar_fused,
            cudaFuncAttributeMaxDynamicSharedMemorySize, SMEM_FLOATS * 4);
        attr_done = true;
    }

    deepar_fused<<<GRID_B + GRID_A, BLK, SMEM_FLOATS * 4>>>(
        X, y, Xf, W_embed, b_embed, W_ih, b_ih, b_hh,
        W_mu, b_mu, W_sigma, b_sigma, out);
}